// round 14
// baseline (speedup 1.0000x reference)
#include <cuda_runtime.h>
#include <math.h>

#define S_LEN 8192
#define B_SZ  32
#define H_SZ  128
#define NMODE 16
#define L_CNT 4

// Inter-layer spectral state: 32 batches x 16 modes x 128 channels, complex.
__device__ float2 g_G[B_SZ][NMODE][H_SZ];  // forward-DFT accumulators (unscaled rfft values)
__device__ float2 g_Y[B_SZ][NMODE][H_SZ];  // mixed + irfft-folded coefficients

typedef unsigned long long u64;

__device__ __forceinline__ u64 pk2(float lo, float hi) {
    u64 r; asm("mov.b64 %0,{%1,%2};" : "=l"(r) : "f"(lo), "f"(hi)); return r;
}
__device__ __forceinline__ void upk2(u64 v, float& lo, float& hi) {
    asm("mov.b64 {%0,%1},%2;" : "=f"(lo), "=f"(hi) : "l"(v));
}
// packed dual-FMA: d = a*b + c (elementwise on f32 pairs)
__device__ __forceinline__ u64 fma2(u64 a, u64 b, u64 c) {
    u64 d; asm("fma.rn.f32x2 %0,%1,%2,%3;" : "=l"(d) : "l"(a), "l"(b), "l"(c)); return d;
}
__device__ __forceinline__ u64 add2(u64 a, u64 b) {
    u64 d; asm("add.rn.f32x2 %0,%1,%2;" : "=l"(d) : "l"(a), "l"(b)); return d;
}
#define SGN2 0x8000000080000000ULL

__device__ __forceinline__ float gelu_exact(float h) {
    return 0.5f * h * (1.0f + erff(h * 0.70710678118654752f));
}

// ---------------------------------------------------------------------------
// Kernel 1: G1[b,m,k] = pw[k] * DFT16(x)[b,m] + S*pb[k]*delta(m,0)
// ---------------------------------------------------------------------------
__global__ __launch_bounds__(256) void fno_dft_x(const float* __restrict__ x,
                                                 const float* __restrict__ pw,
                                                 const float* __restrict__ pb) {
    int b = blockIdx.x;
    int t = threadIdx.x, lane = t & 31, wid = t >> 5;

    float accre[NMODE], accim[NMODE];
#pragma unroll
    for (int m = 0; m < NMODE; m++) { accre[m] = 0.f; accim[m] = 0.f; }

    float c1, s1; sincospif((float)t * (1.0f / 4096.0f), &s1, &c1);
    float cD, sD; sincospif(256.0f / 4096.0f, &sD, &cD);

    for (int it = 0; it < S_LEN / 256; ++it) {
        int s = t + it * 256;
        float xv = x[b * S_LEN + s];
        float c[NMODE], sn[NMODE];
        c[0] = 1.f; sn[0] = 0.f; c[1] = c1; sn[1] = s1;
        float t2 = 2.f * c1;
#pragma unroll
        for (int m = 2; m < NMODE; m++) {
            c[m]  = fmaf(t2, c[m - 1],  -c[m - 2]);
            sn[m] = fmaf(t2, sn[m - 1], -sn[m - 2]);
        }
#pragma unroll
        for (int m = 0; m < NMODE; m++) {
            accre[m] = fmaf(xv, c[m],  accre[m]);
            accim[m] = fmaf(xv, sn[m], accim[m]);
        }
        float nc = fmaf(c1, cD, -s1 * sD);
        float ns = fmaf(c1, sD,  s1 * cD);
        c1 = nc; s1 = ns;
    }

    __shared__ float2 sred[8][NMODE];
    __shared__ float2 sX[NMODE];
#pragma unroll
    for (int m = 0; m < NMODE; m++) {
#pragma unroll
        for (int off = 16; off; off >>= 1) {
            accre[m] += __shfl_xor_sync(0xffffffffu, accre[m], off);
            accim[m] += __shfl_xor_sync(0xffffffffu, accim[m], off);
        }
        if (lane == 0) sred[wid][m] = make_float2(accre[m], accim[m]);
    }
    __syncthreads();
    if (t < NMODE) {
        float xr = 0.f, xi = 0.f;
#pragma unroll
        for (int w = 0; w < 8; w++) { xr += sred[w][t].x; xi += sred[w][t].y; }
        sX[t] = make_float2(xr, -xi);  // e^{-i theta}: negate the sin accumulation
    }
    __syncthreads();

    for (int i = t; i < NMODE * H_SZ; i += 256) {
        int m = i >> 7, k = i & 127;
        float gre = pw[k] * sX[m].x + (m == 0 ? (float)S_LEN * pb[k] : 0.f);
        float gim = pw[k] * sX[m].y;
        g_G[b][m][k] = make_float2(gre, gim);
    }
}

// ---------------------------------------------------------------------------
// Kernel 2 (v3): spectral mix with float4 weight loads + 4-way h split.
// grid (B, 8): block = batch b, 16 k's. Thread t: mg=(t&3)*4 (4 modes),
// kl=(t>>2)&15, hc=t>>6 (h chunk of 32). Weight loads are float4 over the
// contiguous mode dimension; partials reduced across hc via smem.
// irfft folding on write: Y'[0]=(Re/S,0), Y'[m]=(2Re/S,-2Im/S).
// ---------------------------------------------------------------------------
__global__ __launch_bounds__(256) void fno_mix(const float* __restrict__ wre,
                                               const float* __restrict__ wim) {
    int b = blockIdx.x;
    int t = threadIdx.x;
    int mg = (t & 3) * 4;             // first of 4 modes
    int kl = (t >> 2) & 15;           // 0..15
    int hc = t >> 6;                  // 0..3
    int k = blockIdx.y * 16 + kl;

    __shared__ float2 sG[H_SZ][NMODE];       // [h][m], 16 KB
    __shared__ float2 part[4][256];          // [hc][kl*16+m], 8 KB
    for (int i = t; i < NMODE * H_SZ; i += 256) {
        int h = i >> 4, m = i & 15;
        sG[h][m] = g_G[b][m][h];
    }
    __syncthreads();

    const float4* __restrict__ wre4 = (const float4*)wre;
    const float4* __restrict__ wim4 = (const float4*)wim;
    const int base4 = k * 4 + (mg >> 2);     // float4 index within an h-row

    float ar0 = 0.f, ar1 = 0.f, ar2 = 0.f, ar3 = 0.f;
    float ai0 = 0.f, ai1 = 0.f, ai2 = 0.f, ai3 = 0.f;

    int h0 = hc * 32;
#pragma unroll 8
    for (int hh = 0; hh < 32; ++hh) {
        int h = h0 + hh;
        float4 wr = wre4[h * (H_SZ * 4) + base4];
        float4 wi = wim4[h * (H_SZ * 4) + base4];
        const float4* gp = (const float4*)&sG[h][mg];
        float4 gA = gp[0];   // (g0.re, g0.im, g1.re, g1.im)
        float4 gB = gp[1];   // (g2.re, g2.im, g3.re, g3.im)
        ar0 = fmaf(gA.x, wr.x, fmaf(-gA.y, wi.x, ar0));
        ai0 = fmaf(gA.x, wi.x, fmaf( gA.y, wr.x, ai0));
        ar1 = fmaf(gA.z, wr.y, fmaf(-gA.w, wi.y, ar1));
        ai1 = fmaf(gA.z, wi.y, fmaf( gA.w, wr.y, ai1));
        ar2 = fmaf(gB.x, wr.z, fmaf(-gB.y, wi.z, ar2));
        ai2 = fmaf(gB.x, wi.z, fmaf( gB.y, wr.z, ai2));
        ar3 = fmaf(gB.z, wr.w, fmaf(-gB.w, wi.w, ar3));
        ai3 = fmaf(gB.z, wi.w, fmaf( gB.w, wr.w, ai3));
    }

    int obase = kl * 16 + mg;
    part[hc][obase + 0] = make_float2(ar0, ai0);
    part[hc][obase + 1] = make_float2(ar1, ai1);
    part[hc][obase + 2] = make_float2(ar2, ai2);
    part[hc][obase + 3] = make_float2(ar3, ai3);
    __syncthreads();

    // thread t finalizes output o=t: m = t&15, kl = t>>4
    {
        int m = t & 15;
        int ko = blockIdx.y * 16 + (t >> 4);
        float2 p0 = part[0][t], p1 = part[1][t], p2 = part[2][t], p3 = part[3][t];
        float ar = (p0.x + p1.x) + (p2.x + p3.x);
        float ai = (p0.y + p1.y) + (p2.y + p3.y);
        const float invS = 1.0f / (float)S_LEN;
        float are, aim;
        if (m == 0) { are = ar * invS;        aim = 0.f; }
        else        { are = 2.f * ar * invS;  aim = -2.f * ai * invS; }
        g_Y[b][m][ko] = make_float2(are, aim);
    }
}

// ---------------------------------------------------------------------------
// Kernel 3 (hot): fused irfft-recon + GELU + forward-DFT with quartet
// symmetry: one basis eval serves s, 4096-s, 4096+s, 8192-s.
// One warp per (b,k); lane covers s = lane + 32*it, it in [0,64) -> s in [0,2048).
// s==0 duplicates fixed by 0.5 weight; points 2048/6144 added uniformly (1/32).
// ---------------------------------------------------------------------------
__global__ __launch_bounds__(256) void fno_fwd() {
    int gw = (blockIdx.x * 256 + threadIdx.x) >> 5;
    int lane = threadIdx.x & 31;
    int b = gw >> 7, k = gw & 127;

    u64 cf[NMODE];
    float clo[NMODE], chi[NMODE];
#pragma unroll
    for (int m = 0; m < NMODE; m++) {
        float2 y = g_Y[b][m][k];
        cf[m] = pk2(y.x, y.y);
        clo[m] = y.x; chi[m] = y.y;
    }

    // ---- special points s=2048 (theta=pi/2) and s=6144 (3pi/2) ----
    float A = clo[0] - clo[2] + clo[4] - clo[6] + clo[8] - clo[10] + clo[12] - clo[14];
    float Bv = chi[1] - chi[3] + chi[5] - chi[7] + chi[9] - chi[11] + chi[13] - chi[15];
    float g5 = gelu_exact(A + Bv);
    float g6 = gelu_exact(A - Bv);
    float uu = (g5 + g6) * (1.0f / 32.0f);   // uniform across lanes; reduction x32 restores
    float vv = (g5 - g6) * (1.0f / 32.0f);

    u64 P[NMODE];
#pragma unroll
    for (int m = 0; m < NMODE; m++) {
        switch (m & 3) {
            case 0: P[m] = pk2( uu, 0.f); break;
            case 1: P[m] = pk2(0.f,  vv); break;
            case 2: P[m] = pk2(-uu, 0.f); break;
            default:P[m] = pk2(0.f, -vv); break;
        }
    }

    float c1, s1; sincospif((float)lane * (1.0f / 4096.0f), &s1, &c1);
    float cD, sD; sincospif(32.0f / 4096.0f, &sD, &cD);
    const u64 V0 = pk2(1.f, 0.f);
    const u64 ZERO = 0ULL;

    for (int it = 0; it < 64; ++it) {
        // s==0 (lane 0, it 0): quartet double-counts points 0 and 4096 -> 0.5 weight
        float wm = ((it | lane) == 0) ? 0.5f : 1.0f;

        u64 v[NMODE];
        v[0] = V0;
        v[1] = pk2(c1, s1);
        float t2s = 2.f * c1;
        u64 t2 = pk2(t2s, t2s);
#pragma unroll
        for (int m = 2; m < NMODE; m++) v[m] = fma2(t2, v[m - 1], v[m - 2] ^ SGN2);

        u64 E = cf[0];
#pragma unroll
        for (int m = 2; m < NMODE; m += 2) E = fma2(cf[m], v[m], E);
        u64 O = fma2(cf[1], v[1], ZERO);
#pragma unroll
        for (int m = 3; m < NMODE; m += 2) O = fma2(cf[m], v[m], O);

        u64 Pp = add2(E, O);
        u64 Qq = add2(E, O ^ SGN2);
        float pl, ph, ql, qh;
        upk2(Pp, pl, ph); upk2(Qq, ql, qh);
        float h1 = pl + ph;   // s
        float h4 = pl - ph;   // 8192-s
        float h3 = ql + qh;   // 4096+s
        float h2 = ql - qh;   // 4096-s

        float g1 = gelu_exact(h1) * wm;
        float g2 = gelu_exact(h2) * wm;
        float g3 = gelu_exact(h3) * wm;
        float g4 = gelu_exact(h4) * wm;

        float sa = g1 + g4, sb = g2 + g3;
        float sc = g1 - g4, sd = g2 - g3;
        u64 Me = pk2(sa + sb, sc - sd);   // even modes multiplier
        u64 Mo = pk2(sa - sb, sc + sd);   // odd  modes multiplier
#pragma unroll
        for (int m = 0; m < NMODE; m += 2) P[m] = fma2(Me, v[m], P[m]);
#pragma unroll
        for (int m = 1; m < NMODE; m += 2) P[m] = fma2(Mo, v[m], P[m]);

        float nc = fmaf(c1, cD, -s1 * sD);
        float ns = fmaf(c1, sD,  s1 * cD);
        c1 = nc; s1 = ns;
    }

#pragma unroll
    for (int m = 0; m < NMODE; m++) {
        float pre, pim; upk2(P[m], pre, pim);
#pragma unroll
        for (int off = 16; off; off >>= 1) {
            pre += __shfl_xor_sync(0xffffffffu, pre, off);
            pim += __shfl_xor_sync(0xffffffffu, pim, off);
        }
        if (lane == 0) g_G[b][m][k] = make_float2(pre, -pim);  // e^{-i theta}
    }
}

// ---------------------------------------------------------------------------
// Kernel 4: final recon + GELU + output projection with quartet symmetry.
// grid (16, B), 128 threads (thread = channel k). Each iteration i produces
// 4 outputs at {sq, 4096-sq, 4096+sq, 8192-sq}, sq = blockIdx.x*128 + i.
// ---------------------------------------------------------------------------
__global__ __launch_bounds__(128) void fno_final(const float* __restrict__ ow,
                                                 const float* __restrict__ ob,
                                                 float* __restrict__ out) {
    int b = blockIdx.y;
    int y = blockIdx.x;                 // 0..15
    int t = threadIdx.x, lane = t & 31, w = t >> 5;
    int k = t;

    u64 cf[NMODE];
    float clo[NMODE], chi[NMODE];
#pragma unroll
    for (int m = 0; m < NMODE; m++) {
        float2 yv = g_Y[b][m][k];
        cf[m] = pk2(yv.x, yv.y);
        clo[m] = yv.x; chi[m] = yv.y;
    }
    float wk = ow[k];
    float ob0 = ob[0];

    __shared__ float r1[4][128], r2[4][128], r3[4][128], r4[4][128];

    float c1, s1; sincospif((float)(y * 128) * (1.0f / 4096.0f), &s1, &c1);
    float cD, sD; sincospif(1.0f / 4096.0f, &sD, &cD);
    const u64 V0 = pk2(1.f, 0.f);
    const u64 ZERO = 0ULL;

    for (int i = 0; i < 128; ++i) {
        u64 v[NMODE];
        v[0] = V0;
        v[1] = pk2(c1, s1);
        float t2s = 2.f * c1;
        u64 t2 = pk2(t2s, t2s);
#pragma unroll
        for (int m = 2; m < NMODE; m++) v[m] = fma2(t2, v[m - 1], v[m - 2] ^ SGN2);

        u64 E = cf[0];
#pragma unroll
        for (int m = 2; m < NMODE; m += 2) E = fma2(cf[m], v[m], E);
        u64 O = fma2(cf[1], v[1], ZERO);
#pragma unroll
        for (int m = 3; m < NMODE; m += 2) O = fma2(cf[m], v[m], O);

        u64 Pp = add2(E, O);
        u64 Qq = add2(E, O ^ SGN2);
        float pl, ph, ql, qh;
        upk2(Pp, pl, ph); upk2(Qq, ql, qh);
        float p1 = gelu_exact(pl + ph) * wk;   // sq
        float p4 = gelu_exact(pl - ph) * wk;   // 8192-sq
        float p3 = gelu_exact(ql + qh) * wk;   // 4096+sq
        float p2 = gelu_exact(ql - qh) * wk;   // 4096-sq

#pragma unroll
        for (int off = 16; off; off >>= 1) {
            p1 += __shfl_xor_sync(0xffffffffu, p1, off);
            p2 += __shfl_xor_sync(0xffffffffu, p2, off);
            p3 += __shfl_xor_sync(0xffffffffu, p3, off);
            p4 += __shfl_xor_sync(0xffffffffu, p4, off);
        }
        if (lane == 0) { r1[w][i] = p1; r2[w][i] = p2; r3[w][i] = p3; r4[w][i] = p4; }

        float nc = fmaf(c1, cD, -s1 * sD);
        float ns = fmaf(c1, sD,  s1 * cD);
        c1 = nc; s1 = ns;
    }
    __syncthreads();

    // thread t finalizes outputs for i = t
    int sq = y * 128 + t;
    float v1 = r1[0][t] + r1[1][t] + r1[2][t] + r1[3][t] + ob0;
    float v2 = r2[0][t] + r2[1][t] + r2[2][t] + r2[3][t] + ob0;
    float v3 = r3[0][t] + r3[1][t] + r3[2][t] + r3[3][t] + ob0;
    float v4 = r4[0][t] + r4[1][t] + r4[2][t] + r4[3][t] + ob0;
    float* ob_ptr = out + (size_t)b * S_LEN;
    ob_ptr[sq] = v1;
    ob_ptr[4096 - sq] = v2;           // sq==0: duplicates the 4096 write (same value)
    ob_ptr[4096 + sq] = v3;
    if (sq != 0) ob_ptr[8192 - sq] = v4;

    // special outputs s=2048, s=6144 (only block y==0 of each batch)
    if (y == 0) {
        float A = clo[0] - clo[2] + clo[4] - clo[6] + clo[8] - clo[10] + clo[12] - clo[14];
        float Bv = chi[1] - chi[3] + chi[5] - chi[7] + chi[9] - chi[11] + chi[13] - chi[15];
        float p5 = gelu_exact(A + Bv) * wk;
        float p6 = gelu_exact(A - Bv) * wk;
#pragma unroll
        for (int off = 16; off; off >>= 1) {
            p5 += __shfl_xor_sync(0xffffffffu, p5, off);
            p6 += __shfl_xor_sync(0xffffffffu, p6, off);
        }
        __syncthreads();
        if (lane == 0) { r1[w][0] = p5; r2[w][0] = p6; }
        __syncthreads();
        if (t == 0) {
            ob_ptr[2048] = r1[0][0] + r1[1][0] + r1[2][0] + r1[3][0] + ob0;
            ob_ptr[6144] = r2[0][0] + r2[1][0] + r2[2][0] + r2[3][0] + ob0;
        }
    }
}

// ---------------------------------------------------------------------------
extern "C" void kernel_launch(void* const* d_in, const int* in_sizes, int n_in,
                              void* d_out, int out_size) {
    const float* x  = (const float*)d_in[0];
    const float* pw = (const float*)d_in[1];
    const float* pb = (const float*)d_in[2];
    const float* wre = (const float*)d_in[3];
    const float* wim = (const float*)d_in[4];
    const float* ow = (const float*)d_in[5];
    const float* ob = (const float*)d_in[6];
    float* out = (float*)d_out;

    (void)in_sizes; (void)n_in; (void)out_size;

    fno_dft_x<<<B_SZ, 256>>>(x, pw, pb);
    const int loff = H_SZ * H_SZ * NMODE;
    for (int l = 0; l < L_CNT; l++) {
        fno_mix<<<dim3(B_SZ, 8), 256>>>(wre + (size_t)l * loff, wim + (size_t)l * loff);
        if (l < L_CNT - 1) fno_fwd<<<512, 256>>>();
    }
    fno_final<<<dim3(16, B_SZ), 128>>>(ow, ob, out);
}

// round 16
// speedup vs baseline: 1.0061x; 1.0061x over previous
#include <cuda_runtime.h>
#include <math.h>

#define S_LEN 8192
#define B_SZ  32
#define H_SZ  128
#define NMODE 16
#define L_CNT 4

// Inter-layer spectral state: 32 batches x 16 modes x 128 channels, complex.
__device__ float2 g_G[B_SZ][NMODE][H_SZ];  // forward-DFT accumulators (unscaled rfft values)
__device__ float2 g_Y[B_SZ][NMODE][H_SZ];  // mixed + irfft-folded coefficients

typedef unsigned long long u64;

__device__ __forceinline__ u64 pk2(float lo, float hi) {
    u64 r; asm("mov.b64 %0,{%1,%2};" : "=l"(r) : "f"(lo), "f"(hi)); return r;
}
__device__ __forceinline__ void upk2(u64 v, float& lo, float& hi) {
    asm("mov.b64 {%0,%1},%2;" : "=f"(lo), "=f"(hi) : "l"(v));
}
// packed dual-FMA: d = a*b + c (elementwise on f32 pairs)
__device__ __forceinline__ u64 fma2(u64 a, u64 b, u64 c) {
    u64 d; asm("fma.rn.f32x2 %0,%1,%2,%3;" : "=l"(d) : "l"(a), "l"(b), "l"(c)); return d;
}
__device__ __forceinline__ u64 add2(u64 a, u64 b) {
    u64 d; asm("add.rn.f32x2 %0,%1,%2;" : "=l"(d) : "l"(a), "l"(b)); return d;
}
#define SGN2 0x8000000080000000ULL

__device__ __forceinline__ float gelu_exact(float h) {
    return 0.5f * h * (1.0f + erff(h * 0.70710678118654752f));
}

// ---------------------------------------------------------------------------
// Kernel 1: G1[b,m,k] = pw[k] * DFT16(x)[b,m] + S*pb[k]*delta(m,0)
// ---------------------------------------------------------------------------
__global__ __launch_bounds__(256) void fno_dft_x(const float* __restrict__ x,
                                                 const float* __restrict__ pw,
                                                 const float* __restrict__ pb) {
    int b = blockIdx.x;
    int t = threadIdx.x, lane = t & 31, wid = t >> 5;

    float accre[NMODE], accim[NMODE];
#pragma unroll
    for (int m = 0; m < NMODE; m++) { accre[m] = 0.f; accim[m] = 0.f; }

    float c1, s1; sincospif((float)t * (1.0f / 4096.0f), &s1, &c1);
    float cD, sD; sincospif(256.0f / 4096.0f, &sD, &cD);

    for (int it = 0; it < S_LEN / 256; ++it) {
        int s = t + it * 256;
        float xv = x[b * S_LEN + s];
        float c[NMODE], sn[NMODE];
        c[0] = 1.f; sn[0] = 0.f; c[1] = c1; sn[1] = s1;
        float t2 = 2.f * c1;
#pragma unroll
        for (int m = 2; m < NMODE; m++) {
            c[m]  = fmaf(t2, c[m - 1],  -c[m - 2]);
            sn[m] = fmaf(t2, sn[m - 1], -sn[m - 2]);
        }
#pragma unroll
        for (int m = 0; m < NMODE; m++) {
            accre[m] = fmaf(xv, c[m],  accre[m]);
            accim[m] = fmaf(xv, sn[m], accim[m]);
        }
        float nc = fmaf(c1, cD, -s1 * sD);
        float ns = fmaf(c1, sD,  s1 * cD);
        c1 = nc; s1 = ns;
    }

    __shared__ float2 sred[8][NMODE];
    __shared__ float2 sX[NMODE];
#pragma unroll
    for (int m = 0; m < NMODE; m++) {
#pragma unroll
        for (int off = 16; off; off >>= 1) {
            accre[m] += __shfl_xor_sync(0xffffffffu, accre[m], off);
            accim[m] += __shfl_xor_sync(0xffffffffu, accim[m], off);
        }
        if (lane == 0) sred[wid][m] = make_float2(accre[m], accim[m]);
    }
    __syncthreads();
    if (t < NMODE) {
        float xr = 0.f, xi = 0.f;
#pragma unroll
        for (int w = 0; w < 8; w++) { xr += sred[w][t].x; xi += sred[w][t].y; }
        sX[t] = make_float2(xr, -xi);  // e^{-i theta}: negate the sin accumulation
    }
    __syncthreads();

    for (int i = t; i < NMODE * H_SZ; i += 256) {
        int m = i >> 7, k = i & 127;
        float gre = pw[k] * sX[m].x + (m == 0 ? (float)S_LEN * pb[k] : 0.f);
        float gim = pw[k] * sX[m].y;
        g_G[b][m][k] = make_float2(gre, gim);
    }
}

// ---------------------------------------------------------------------------
// Kernel 2 (v3): spectral mix with float4 weight loads + 4-way h split.
// grid (B, 8): block = batch b, 16 k's. Thread t: mg=(t&3)*4 (4 modes),
// kl=(t>>2)&15, hc=t>>6 (h chunk of 32). Weight loads are float4 over the
// contiguous mode dimension; partials reduced across hc via smem.
// irfft folding on write: Y'[0]=(Re/S,0), Y'[m]=(2Re/S,-2Im/S).
// ---------------------------------------------------------------------------
__global__ __launch_bounds__(256) void fno_mix(const float* __restrict__ wre,
                                               const float* __restrict__ wim) {
    int b = blockIdx.x;
    int t = threadIdx.x;
    int mg = (t & 3) * 4;             // first of 4 modes
    int kl = (t >> 2) & 15;           // 0..15
    int hc = t >> 6;                  // 0..3
    int k = blockIdx.y * 16 + kl;

    __shared__ float2 sG[H_SZ][NMODE];       // [h][m], 16 KB
    __shared__ float2 part[4][256];          // [hc][kl*16+m], 8 KB
    for (int i = t; i < NMODE * H_SZ; i += 256) {
        int h = i >> 4, m = i & 15;
        sG[h][m] = g_G[b][m][h];
    }
    __syncthreads();

    const float4* __restrict__ wre4 = (const float4*)wre;
    const float4* __restrict__ wim4 = (const float4*)wim;
    const int base4 = k * 4 + (mg >> 2);     // float4 index within an h-row

    float ar0 = 0.f, ar1 = 0.f, ar2 = 0.f, ar3 = 0.f;
    float ai0 = 0.f, ai1 = 0.f, ai2 = 0.f, ai3 = 0.f;

    int h0 = hc * 32;
#pragma unroll 8
    for (int hh = 0; hh < 32; ++hh) {
        int h = h0 + hh;
        float4 wr = wre4[h * (H_SZ * 4) + base4];
        float4 wi = wim4[h * (H_SZ * 4) + base4];
        const float4* gp = (const float4*)&sG[h][mg];
        float4 gA = gp[0];   // (g0.re, g0.im, g1.re, g1.im)
        float4 gB = gp[1];   // (g2.re, g2.im, g3.re, g3.im)
        ar0 = fmaf(gA.x, wr.x, fmaf(-gA.y, wi.x, ar0));
        ai0 = fmaf(gA.x, wi.x, fmaf( gA.y, wr.x, ai0));
        ar1 = fmaf(gA.z, wr.y, fmaf(-gA.w, wi.y, ar1));
        ai1 = fmaf(gA.z, wi.y, fmaf( gA.w, wr.y, ai1));
        ar2 = fmaf(gB.x, wr.z, fmaf(-gB.y, wi.z, ar2));
        ai2 = fmaf(gB.x, wi.z, fmaf( gB.y, wr.z, ai2));
        ar3 = fmaf(gB.z, wr.w, fmaf(-gB.w, wi.w, ar3));
        ai3 = fmaf(gB.z, wi.w, fmaf( gB.w, wr.w, ai3));
    }

    int obase = kl * 16 + mg;
    part[hc][obase + 0] = make_float2(ar0, ai0);
    part[hc][obase + 1] = make_float2(ar1, ai1);
    part[hc][obase + 2] = make_float2(ar2, ai2);
    part[hc][obase + 3] = make_float2(ar3, ai3);
    __syncthreads();

    // thread t finalizes output o=t: m = t&15, kl = t>>4
    {
        int m = t & 15;
        int ko = blockIdx.y * 16 + (t >> 4);
        float2 p0 = part[0][t], p1 = part[1][t], p2 = part[2][t], p3 = part[3][t];
        float ar = (p0.x + p1.x) + (p2.x + p3.x);
        float ai = (p0.y + p1.y) + (p2.y + p3.y);
        const float invS = 1.0f / (float)S_LEN;
        float are, aim;
        if (m == 0) { are = ar * invS;        aim = 0.f; }
        else        { are = 2.f * ar * invS;  aim = -2.f * ai * invS; }
        g_Y[b][m][ko] = make_float2(are, aim);
    }
}

// ---------------------------------------------------------------------------
// Kernel 3 (hot): fused irfft-recon + GELU + forward-DFT with quartet
// symmetry: one basis eval serves s, 4096-s, 4096+s, 8192-s.
// One warp per (b,k); lane covers s = lane + 32*it, it in [0,64) -> s in [0,2048).
// s==0 duplicates fixed by 0.5 weight; points 2048/6144 added uniformly (1/32).
// ---------------------------------------------------------------------------
__global__ __launch_bounds__(256) void fno_fwd() {
    int gw = (blockIdx.x * 256 + threadIdx.x) >> 5;
    int lane = threadIdx.x & 31;
    int b = gw >> 7, k = gw & 127;

    u64 cf[NMODE];
    float clo[NMODE], chi[NMODE];
#pragma unroll
    for (int m = 0; m < NMODE; m++) {
        float2 y = g_Y[b][m][k];
        cf[m] = pk2(y.x, y.y);
        clo[m] = y.x; chi[m] = y.y;
    }

    // ---- special points s=2048 (theta=pi/2) and s=6144 (3pi/2) ----
    float A = clo[0] - clo[2] + clo[4] - clo[6] + clo[8] - clo[10] + clo[12] - clo[14];
    float Bv = chi[1] - chi[3] + chi[5] - chi[7] + chi[9] - chi[11] + chi[13] - chi[15];
    float g5 = gelu_exact(A + Bv);
    float g6 = gelu_exact(A - Bv);
    float uu = (g5 + g6) * (1.0f / 32.0f);   // uniform across lanes; reduction x32 restores
    float vv = (g5 - g6) * (1.0f / 32.0f);

    u64 P[NMODE];
#pragma unroll
    for (int m = 0; m < NMODE; m++) {
        switch (m & 3) {
            case 0: P[m] = pk2( uu, 0.f); break;
            case 1: P[m] = pk2(0.f,  vv); break;
            case 2: P[m] = pk2(-uu, 0.f); break;
            default:P[m] = pk2(0.f, -vv); break;
        }
    }

    float c1, s1; sincospif((float)lane * (1.0f / 4096.0f), &s1, &c1);
    float cD, sD; sincospif(32.0f / 4096.0f, &sD, &cD);
    const u64 V0 = pk2(1.f, 0.f);
    const u64 ZERO = 0ULL;

    for (int it = 0; it < 64; ++it) {
        // s==0 (lane 0, it 0): quartet double-counts points 0 and 4096 -> 0.5 weight
        float wm = ((it | lane) == 0) ? 0.5f : 1.0f;

        u64 v[NMODE];
        v[0] = V0;
        v[1] = pk2(c1, s1);
        float t2s = 2.f * c1;
        u64 t2 = pk2(t2s, t2s);
#pragma unroll
        for (int m = 2; m < NMODE; m++) v[m] = fma2(t2, v[m - 1], v[m - 2] ^ SGN2);

        u64 E = cf[0];
#pragma unroll
        for (int m = 2; m < NMODE; m += 2) E = fma2(cf[m], v[m], E);
        u64 O = fma2(cf[1], v[1], ZERO);
#pragma unroll
        for (int m = 3; m < NMODE; m += 2) O = fma2(cf[m], v[m], O);

        u64 Pp = add2(E, O);
        u64 Qq = add2(E, O ^ SGN2);
        float pl, ph, ql, qh;
        upk2(Pp, pl, ph); upk2(Qq, ql, qh);
        float h1 = pl + ph;   // s
        float h4 = pl - ph;   // 8192-s
        float h3 = ql + qh;   // 4096+s
        float h2 = ql - qh;   // 4096-s

        float g1 = gelu_exact(h1) * wm;
        float g2 = gelu_exact(h2) * wm;
        float g3 = gelu_exact(h3) * wm;
        float g4 = gelu_exact(h4) * wm;

        float sa = g1 + g4, sb = g2 + g3;
        float sc = g1 - g4, sd = g2 - g3;
        u64 Me = pk2(sa + sb, sc - sd);   // even modes multiplier
        u64 Mo = pk2(sa - sb, sc + sd);   // odd  modes multiplier
#pragma unroll
        for (int m = 0; m < NMODE; m += 2) P[m] = fma2(Me, v[m], P[m]);
#pragma unroll
        for (int m = 1; m < NMODE; m += 2) P[m] = fma2(Mo, v[m], P[m]);

        float nc = fmaf(c1, cD, -s1 * sD);
        float ns = fmaf(c1, sD,  s1 * cD);
        c1 = nc; s1 = ns;
    }

#pragma unroll
    for (int m = 0; m < NMODE; m++) {
        float pre, pim; upk2(P[m], pre, pim);
#pragma unroll
        for (int off = 16; off; off >>= 1) {
            pre += __shfl_xor_sync(0xffffffffu, pre, off);
            pim += __shfl_xor_sync(0xffffffffu, pim, off);
        }
        if (lane == 0) g_G[b][m][k] = make_float2(pre, -pim);  // e^{-i theta}
    }
}

// ---------------------------------------------------------------------------
// Kernel 4: final recon + GELU + output projection with quartet symmetry.
// grid (16, B), 128 threads (thread = channel k). Each iteration i produces
// 4 outputs at {sq, 4096-sq, 4096+sq, 8192-sq}, sq = blockIdx.x*128 + i.
// ---------------------------------------------------------------------------
__global__ __launch_bounds__(128) void fno_final(const float* __restrict__ ow,
                                                 const float* __restrict__ ob,
                                                 float* __restrict__ out) {
    int b = blockIdx.y;
    int y = blockIdx.x;                 // 0..15
    int t = threadIdx.x, lane = t & 31, w = t >> 5;
    int k = t;

    u64 cf[NMODE];
    float clo[NMODE], chi[NMODE];
#pragma unroll
    for (int m = 0; m < NMODE; m++) {
        float2 yv = g_Y[b][m][k];
        cf[m] = pk2(yv.x, yv.y);
        clo[m] = yv.x; chi[m] = yv.y;
    }
    float wk = ow[k];
    float ob0 = ob[0];

    __shared__ float r1[4][128], r2[4][128], r3[4][128], r4[4][128];

    float c1, s1; sincospif((float)(y * 128) * (1.0f / 4096.0f), &s1, &c1);
    float cD, sD; sincospif(1.0f / 4096.0f, &sD, &cD);
    const u64 V0 = pk2(1.f, 0.f);
    const u64 ZERO = 0ULL;

    for (int i = 0; i < 128; ++i) {
        u64 v[NMODE];
        v[0] = V0;
        v[1] = pk2(c1, s1);
        float t2s = 2.f * c1;
        u64 t2 = pk2(t2s, t2s);
#pragma unroll
        for (int m = 2; m < NMODE; m++) v[m] = fma2(t2, v[m - 1], v[m - 2] ^ SGN2);

        u64 E = cf[0];
#pragma unroll
        for (int m = 2; m < NMODE; m += 2) E = fma2(cf[m], v[m], E);
        u64 O = fma2(cf[1], v[1], ZERO);
#pragma unroll
        for (int m = 3; m < NMODE; m += 2) O = fma2(cf[m], v[m], O);

        u64 Pp = add2(E, O);
        u64 Qq = add2(E, O ^ SGN2);
        float pl, ph, ql, qh;
        upk2(Pp, pl, ph); upk2(Qq, ql, qh);
        float p1 = gelu_exact(pl + ph) * wk;   // sq
        float p4 = gelu_exact(pl - ph) * wk;   // 8192-sq
        float p3 = gelu_exact(ql + qh) * wk;   // 4096+sq
        float p2 = gelu_exact(ql - qh) * wk;   // 4096-sq

#pragma unroll
        for (int off = 16; off; off >>= 1) {
            p1 += __shfl_xor_sync(0xffffffffu, p1, off);
            p2 += __shfl_xor_sync(0xffffffffu, p2, off);
            p3 += __shfl_xor_sync(0xffffffffu, p3, off);
            p4 += __shfl_xor_sync(0xffffffffu, p4, off);
        }
        if (lane == 0) { r1[w][i] = p1; r2[w][i] = p2; r3[w][i] = p3; r4[w][i] = p4; }

        float nc = fmaf(c1, cD, -s1 * sD);
        float ns = fmaf(c1, sD,  s1 * cD);
        c1 = nc; s1 = ns;
    }
    __syncthreads();

    // thread t finalizes outputs for i = t
    int sq = y * 128 + t;
    float v1 = r1[0][t] + r1[1][t] + r1[2][t] + r1[3][t] + ob0;
    float v2 = r2[0][t] + r2[1][t] + r2[2][t] + r2[3][t] + ob0;
    float v3 = r3[0][t] + r3[1][t] + r3[2][t] + r3[3][t] + ob0;
    float v4 = r4[0][t] + r4[1][t] + r4[2][t] + r4[3][t] + ob0;
    float* ob_ptr = out + (size_t)b * S_LEN;
    ob_ptr[sq] = v1;
    ob_ptr[4096 - sq] = v2;           // sq==0: duplicates the 4096 write (same value)
    ob_ptr[4096 + sq] = v3;
    if (sq != 0) ob_ptr[8192 - sq] = v4;

    // special outputs s=2048, s=6144 (only block y==0 of each batch)
    if (y == 0) {
        float A = clo[0] - clo[2] + clo[4] - clo[6] + clo[8] - clo[10] + clo[12] - clo[14];
        float Bv = chi[1] - chi[3] + chi[5] - chi[7] + chi[9] - chi[11] + chi[13] - chi[15];
        float p5 = gelu_exact(A + Bv) * wk;
        float p6 = gelu_exact(A - Bv) * wk;
#pragma unroll
        for (int off = 16; off; off >>= 1) {
            p5 += __shfl_xor_sync(0xffffffffu, p5, off);
            p6 += __shfl_xor_sync(0xffffffffu, p6, off);
        }
        __syncthreads();
        if (lane == 0) { r1[w][0] = p5; r2[w][0] = p6; }
        __syncthreads();
        if (t == 0) {
            ob_ptr[2048] = r1[0][0] + r1[1][0] + r1[2][0] + r1[3][0] + ob0;
            ob_ptr[6144] = r2[0][0] + r2[1][0] + r2[2][0] + r2[3][0] + ob0;
        }
    }
}

// ---------------------------------------------------------------------------
extern "C" void kernel_launch(void* const* d_in, const int* in_sizes, int n_in,
                              void* d_out, int out_size) {
    const float* x  = (const float*)d_in[0];
    const float* pw = (const float*)d_in[1];
    const float* pb = (const float*)d_in[2];
    const float* wre = (const float*)d_in[3];
    const float* wim = (const float*)d_in[4];
    const float* ow = (const float*)d_in[5];
    const float* ob = (const float*)d_in[6];
    float* out = (float*)d_out;

    (void)in_sizes; (void)n_in; (void)out_size;

    fno_dft_x<<<B_SZ, 256>>>(x, pw, pb);
    const int loff = H_SZ * H_SZ * NMODE;
    for (int l = 0; l < L_CNT; l++) {
        fno_mix<<<dim3(B_SZ, 8), 256>>>(wre + (size_t)l * loff, wim + (size_t)l * loff);
        if (l < L_CNT - 1) fno_fwd<<<512, 256>>>();
    }
    fno_final<<<dim3(16, B_SZ), 128>>>(ow, ob, out);
}